// round 15
// baseline (speedup 1.0000x reference)
#include <cuda_runtime.h>
#include <cuda_bf16.h>
#include <math.h>
#include <stdint.h>

#define BSZ 4
#define SEQ 2048
#define HIDDIM 2048
#define NH 16
#define HDIM 128
#define MTOT (BSZ * SEQ)   // 8192
#define QKSCALE 0.08838834764831845f
#define QSCALE2 (QKSCALE * 1.4426950408889634f)   // fold log2(e): softmax in 2^x

// ---------------------------------------------------------------------------
// Scratch (static __device__ — no allocations allowed)
// ---------------------------------------------------------------------------
__device__ __nv_bfloat16 g_xhi[(size_t)MTOT * HIDDIM];
__device__ __nv_bfloat16 g_xlo[(size_t)MTOT * HIDDIM];
__device__ __nv_bfloat16 g_whi[(size_t)4 * HIDDIM * HIDDIM];   // [Wq|Wk|Wv|Wo]
__device__ __nv_bfloat16 g_wlo[(size_t)4 * HIDDIM * HIDDIM];
__device__ __nv_bfloat16 g_chi[(size_t)MTOT * HIDDIM];
__device__ __nv_bfloat16 g_clo[(size_t)MTOT * HIDDIM];
__device__ __nv_bfloat16 g_qhi[(size_t)MTOT * HIDDIM];         // [B,H,S,D] log2-scaled
__device__ __nv_bfloat16 g_qlo[(size_t)MTOT * HIDDIM];
__device__ __nv_bfloat16 g_khi[(size_t)MTOT * HIDDIM];
__device__ __nv_bfloat16 g_klo[(size_t)MTOT * HIDDIM];
__device__ __nv_bfloat16 g_vhi[(size_t)MTOT * HIDDIM];
__device__ __nv_bfloat16 g_vlo[(size_t)MTOT * HIDDIM];

// ---------------------------------------------------------------------------
// Portable (compute_80+) tensor-core helpers
// ---------------------------------------------------------------------------
__device__ __forceinline__ uint32_t smem_u32(const void* p) {
    uint32_t a;
    asm("{ .reg .u64 t; cvta.to.shared.u64 t, %1; cvt.u32.u64 %0, t; }" : "=r"(a) : "l"(p));
    return a;
}
__device__ __forceinline__ void cp_async16(uint32_t dst, const void* src) {
    asm volatile("cp.async.cg.shared.global [%0], [%1], 16;" :: "r"(dst), "l"(src) : "memory");
}
__device__ __forceinline__ void cp_commit() {
    asm volatile("cp.async.commit_group;" ::: "memory");
}
template <int N>
__device__ __forceinline__ void cp_wait() {
    asm volatile("cp.async.wait_group %0;" :: "n"(N) : "memory");
}
__device__ __forceinline__ void ldsm_x4(uint32_t* r, uint32_t addr) {
    asm volatile("ldmatrix.sync.aligned.m8n8.x4.shared.b16 {%0,%1,%2,%3}, [%4];"
                 : "=r"(r[0]), "=r"(r[1]), "=r"(r[2]), "=r"(r[3]) : "r"(addr));
}
__device__ __forceinline__ void ldsm_x4_t(uint32_t* r, uint32_t addr) {
    asm volatile("ldmatrix.sync.aligned.m8n8.x4.trans.shared.b16 {%0,%1,%2,%3}, [%4];"
                 : "=r"(r[0]), "=r"(r[1]), "=r"(r[2]), "=r"(r[3]) : "r"(addr));
}
__device__ __forceinline__ void mma_16816(float* c, const uint32_t* a, const uint32_t* b) {
    asm volatile(
        "mma.sync.aligned.m16n8k16.row.col.f32.bf16.bf16.f32 "
        "{%0,%1,%2,%3}, {%4,%5,%6,%7}, {%8,%9}, {%0,%1,%2,%3};"
        : "+f"(c[0]), "+f"(c[1]), "+f"(c[2]), "+f"(c[3])
        : "r"(a[0]), "r"(a[1]), "r"(a[2]), "r"(a[3]), "r"(b[0]), "r"(b[1]));
}

__device__ __forceinline__ void split2(float a, float b, uint32_t& hi, uint32_t& lo) {
    __nv_bfloat16 ha = __float2bfloat16_rn(a), hb = __float2bfloat16_rn(b);
    __nv_bfloat16 la = __float2bfloat16_rn(a - __bfloat162float(ha));
    __nv_bfloat16 lb = __float2bfloat16_rn(b - __bfloat162float(hb));
    hi = (uint32_t)__bfloat16_as_ushort(ha) | ((uint32_t)__bfloat16_as_ushort(hb) << 16);
    lo = (uint32_t)__bfloat16_as_ushort(la) | ((uint32_t)__bfloat16_as_ushort(lb) << 16);
}

// FFMA-pipe 2^x: x <= ~0, handles -inf via clamp. rel err ~1e-7.
__device__ __forceinline__ float fexp2(float t) {
    t = fmaxf(t, -126.0f);
    float fi = t + 12582912.0f;
    int i = __float_as_int(fi) - 0x4B400000;
    float r = t - (fi - 12582912.0f);
    float p = 1.8775767e-3f;
    p = fmaf(p, r, 8.9893397e-3f);
    p = fmaf(p, r, 5.5826318e-2f);
    p = fmaf(p, r, 2.4015361e-1f);
    p = fmaf(p, r, 6.9315308e-1f);
    p = fmaf(p, r, 1.0f);
    return p * __int_as_float((i + 127) << 23);
}

// ---------------------------------------------------------------------------
// fp32 -> bf16 hi/lo splits
// ---------------------------------------------------------------------------
__global__ void split_f32(const float* __restrict__ src, __nv_bfloat16* __restrict__ hi,
                          __nv_bfloat16* __restrict__ lo, int n4)
{
    int i = blockIdx.x * blockDim.x + threadIdx.x;
    if (i >= n4) return;
    float4 v = ((const float4*)src)[i];
    uint32_t h0, l0, h1, l1;
    split2(v.x, v.y, h0, l0);
    split2(v.z, v.w, h1, l1);
    ((uint2*)hi)[i] = make_uint2(h0, h1);
    ((uint2*)lo)[i] = make_uint2(l0, l1);
}

__global__ void split_w4(const float* __restrict__ Wq, const float* __restrict__ Wk,
                         const float* __restrict__ Wv, const float* __restrict__ Wo,
                         __nv_bfloat16* __restrict__ hi, __nv_bfloat16* __restrict__ lo)
{
    const int per = (HIDDIM * HIDDIM) / 4;
    int i = blockIdx.x * blockDim.x + threadIdx.x;
    int w = i / per, j = i - w * per;
    const float* src = (w == 0) ? Wq : (w == 1) ? Wk : (w == 2) ? Wv : Wo;
    float4 v = ((const float4*)src)[j];
    uint32_t h0, l0, h1, l1;
    split2(v.x, v.y, h0, l0);
    split2(v.z, v.w, h1, l1);
    ((uint2*)hi)[i] = make_uint2(h0, h1);
    ((uint2*)lo)[i] = make_uint2(l0, l1);
}

// ---------------------------------------------------------------------------
// mma.sync bf16x3 NT GEMM, 256x128 CTA tile, 8 warps of 64x64, double-buffered
// cp.async (96 KB/stage), single __syncthreads per K-chunk.
// mode 0: fp32 row-major C [M, HIDDIM]
// mode 3: merged QKV (N=6144): sel=col>>11 -> 0:q (scaled, split only),
//         1:k / 2:v (fp32 kv cache + split)
// ---------------------------------------------------------------------------
#define KC 64
#define A_B   (256 * 128)            // 32 KB (one A half, hi or lo)
#define B_B   (128 * 128)            // 16 KB
#define STG_B (2 * A_B + 2 * B_B)    // 96 KB per stage
#define NCHUNK (HIDDIM / KC)         // 32

__global__ void __launch_bounds__(256, 1)
gemm_mma(const __nv_bfloat16* __restrict__ Ahi, const __nv_bfloat16* __restrict__ Alo,
         const __nv_bfloat16* __restrict__ Bhi, const __nv_bfloat16* __restrict__ Blo,
         float* __restrict__ C, int mode,
         __nv_bfloat16* __restrict__ qhi, __nv_bfloat16* __restrict__ qlo,
         __nv_bfloat16* __restrict__ khi, __nv_bfloat16* __restrict__ klo,
         __nv_bfloat16* __restrict__ vhi, __nv_bfloat16* __restrict__ vlo)
{
    extern __shared__ char dsm[];
    const int tid  = threadIdx.x;
    const int wid  = tid >> 5;
    const int lane = tid & 31;
    const int wm   = wid & 3;            // 4 row-slabs of 64
    const int wn   = wid >> 2;           // 2 col-slabs of 64
    const int bm = blockIdx.y * 256;
    const int bn = blockIdx.x * 128;
    const uint32_t smb = smem_u32(dsm);

    float acc[4][8][4];
#pragma unroll
    for (int mi = 0; mi < 4; mi++)
#pragma unroll
        for (int ni = 0; ni < 8; ni++)
#pragma unroll
            for (int t = 0; t < 4; t++) acc[mi][ni][t] = 0.f;

    const int lr = tid >> 3;             // 0..31
    const int lc = tid & 7;

    auto issue_stage = [&](int st, int kc) {
        uint32_t sbase = smb + st * STG_B;
        const size_t kb = (size_t)kc * KC;
#pragma unroll
        for (int it = 0; it < 8; it++) {                 // A: 256 rows
            int r = lr + it * 32;
            int sw = ((lc ^ (r & 7)) << 4);
            size_t ga = (size_t)(bm + r) * HIDDIM + kb + lc * 8;
            cp_async16(sbase + r * 128 + sw,        Ahi + ga);
            cp_async16(sbase + A_B + r * 128 + sw,  Alo + ga);
        }
#pragma unroll
        for (int it = 0; it < 4; it++) {                 // B: 128 rows
            int r = lr + it * 32;
            int sw = ((lc ^ (r & 7)) << 4);
            size_t gb = (size_t)(bn + r) * HIDDIM + kb + lc * 8;
            cp_async16(sbase + 2 * A_B + r * 128 + sw,        Bhi + gb);
            cp_async16(sbase + 2 * A_B + B_B + r * 128 + sw,  Blo + gb);
        }
        cp_commit();
    };

    issue_stage(0, 0);

    for (int kc = 0; kc < NCHUNK; kc++) {
        cp_wait<0>();
        __syncthreads();                 // data visible + prior stage retired
        if (kc + 1 < NCHUNK) issue_stage((kc + 1) & 1, kc + 1);

        const uint32_t sb = smb + (kc & 1) * STG_B;
        const int arow_l = (lane & 15);
        const int koff_l = (lane >> 4);

#pragma unroll
        for (int ks = 0; ks < 4; ks++) {
            const int chunk = ks * 2 + koff_l;
            uint32_t ahi[4][4], alo[4][4];
#pragma unroll
            for (int mi = 0; mi < 4; mi++) {
                int r = wm * 64 + mi * 16 + arow_l;
                uint32_t off = (uint32_t)(r * 128 + ((chunk ^ (r & 7)) << 4));
                ldsm_x4(ahi[mi], sb + off);
                ldsm_x4(alo[mi], sb + A_B + off);
            }
            uint32_t bhi[8][2], blo[8][2];
#pragma unroll
            for (int g = 0; g < 4; g++) {
                int r = wn * 64 + g * 16 + arow_l;
                uint32_t off = (uint32_t)(r * 128 + ((chunk ^ (r & 7)) << 4));
                uint32_t t[4];
                ldsm_x4(t, sb + 2 * A_B + off);
                bhi[g * 2 + 0][0] = t[0]; bhi[g * 2 + 1][0] = t[1];
                bhi[g * 2 + 0][1] = t[2]; bhi[g * 2 + 1][1] = t[3];
                ldsm_x4(t, sb + 2 * A_B + B_B + off);
                blo[g * 2 + 0][0] = t[0]; blo[g * 2 + 1][0] = t[1];
                blo[g * 2 + 0][1] = t[2]; blo[g * 2 + 1][1] = t[3];
            }
#pragma unroll
            for (int mi = 0; mi < 4; mi++)
#pragma unroll
                for (int ni = 0; ni < 8; ni++) {
                    mma_16816(acc[mi][ni], ahi[mi], bhi[ni]);
                    mma_16816(acc[mi][ni], ahi[mi], blo[ni]);
                    mma_16816(acc[mi][ni], alo[mi], bhi[ni]);
                }
        }
    }

    // epilogue
#pragma unroll
    for (int mi = 0; mi < 4; mi++) {
        const int row0 = bm + wm * 64 + mi * 16 + (lane >> 2);
#pragma unroll
        for (int half = 0; half < 2; half++) {
            const int row = row0 + half * 8;
            const int b = row >> 11, s = row & 2047;
#pragma unroll
            for (int ni = 0; ni < 8; ni++) {
                const int col = bn + wn * 64 + ni * 8 + (lane & 3) * 2;
                float v0 = acc[mi][ni][half * 2 + 0];
                float v1 = acc[mi][ni][half * 2 + 1];
                if (mode == 0) {
                    *(float2*)(C + (size_t)row * HIDDIM + col) = make_float2(v0, v1);
                } else {
                    const int sel = col >> 11;          // 0 q, 1 k, 2 v
                    const int cm = col & 2047;
                    const int h = cm >> 7, d = cm & 127;
                    const size_t sc = (((size_t)b * NH + h) * SEQ + s) * HDIM + d;
                    uint32_t hw, lw;
                    if (sel == 0) {
                        split2(v0 * QSCALE2, v1 * QSCALE2, hw, lw);
                        *(uint32_t*)(qhi + sc) = hw;
                        *(uint32_t*)(qlo + sc) = lw;
                    } else {
                        size_t kva = ((((size_t)b * NH + h) * 2 + (sel - 1)) * SEQ + s) * HDIM + d;
                        *(float2*)(C + kva) = make_float2(v0, v1);
                        split2(v0, v1, hw, lw);
                        __nv_bfloat16* sh = (sel == 1) ? khi : vhi;
                        __nv_bfloat16* sl = (sel == 1) ? klo : vlo;
                        *(uint32_t*)(sh + sc) = hw;
                        *(uint32_t*)(sl + sc) = lw;
                    }
                }
            }
        }
    }
}

// ---------------------------------------------------------------------------
// Tensor-core flash attention: causal, q-tile 128, k-tile 64, 8 warps,
// exp2-domain online softmax, single __syncthreads per k-tile.
// ---------------------------------------------------------------------------
#define FA_SMEM (65536 + 2 * 65536)   // 192 KB

__global__ void __launch_bounds__(256, 1)
flash_attn_tc(const __nv_bfloat16* __restrict__ Qhi, const __nv_bfloat16* __restrict__ Qlo,
              const __nv_bfloat16* __restrict__ Khi, const __nv_bfloat16* __restrict__ Klo,
              const __nv_bfloat16* __restrict__ Vhi, const __nv_bfloat16* __restrict__ Vlo,
              __nv_bfloat16* __restrict__ chi, __nv_bfloat16* __restrict__ clo)
{
    extern __shared__ char dsm[];
    const int tid = threadIdx.x, wid = tid >> 5, lane = tid & 31;
    const int qt = 15 - blockIdx.x;          // big tiles first
    const int bh = blockIdx.y;
    const uint32_t smb = smem_u32(dsm);
    const uint32_t sQh = smb, sQl = smb + 32768;

    const size_t bhb = (size_t)bh * SEQ * HDIM;
    const __nv_bfloat16* qh_g = Qhi + bhb + (size_t)qt * 128 * HDIM;
    const __nv_bfloat16* ql_g = Qlo + bhb + (size_t)qt * 128 * HDIM;

#pragma unroll
    for (int it = 0; it < 8; it++) {
        int idx = tid + it * 256;
        int r = idx >> 4, c = idx & 15;
        uint32_t off = r * 256 + ((c ^ (r & 7)) << 4);
        int g = r * 128 + c * 8;
        cp_async16(sQh + off, qh_g + g);
        cp_async16(sQl + off, ql_g + g);
    }

    auto load_kv = [&](int st, int kt) {
        uint32_t sb = smb + 65536 + st * 65536;
        const size_t tb = bhb + (size_t)kt * 64 * HDIM;
#pragma unroll
        for (int it = 0; it < 4; it++) {
            int idx = tid + it * 256;
            int r = idx >> 4, c = idx & 15;
            uint32_t off = r * 256 + ((c ^ (r & 7)) << 4);
            int g = r * 128 + c * 8;
            cp_async16(sb + off,         Khi + tb + g);
            cp_async16(sb + 16384 + off, Klo + tb + g);
            cp_async16(sb + 32768 + off, Vhi + tb + g);
            cp_async16(sb + 49152 + off, Vlo + tb + g);
        }
        cp_commit();
    };
    load_kv(0, 0);

    float o[16][4];
#pragma unroll
    for (int nb = 0; nb < 16; nb++)
#pragma unroll
        for (int t = 0; t < 4; t++) o[nb][t] = 0.f;
    float m0 = -INFINITY, m1 = -INFINITY, l0 = 0.f, l1 = 0.f;

    const int ktmax = 2 * qt + 1;
    for (int kt = 0; kt <= ktmax; kt++) {
        const int st = kt & 1;
        cp_wait<0>();
        __syncthreads();
        if (kt < ktmax) load_kv(st ^ 1, kt + 1);

        const uint32_t sb = smb + 65536 + st * 65536;
        const uint32_t sKh = sb, sKl = sb + 16384, sVh = sb + 32768, sVl = sb + 49152;

        float s[8][4];
#pragma unroll
        for (int nb = 0; nb < 8; nb++)
#pragma unroll
            for (int t = 0; t < 4; t++) s[nb][t] = 0.f;

#pragma unroll
        for (int ks = 0; ks < 8; ks++) {
            const int c = ks * 2 + (lane >> 4);
            const int qr = wid * 16 + (lane & 15);
            uint32_t qoff = qr * 256 + ((c ^ (qr & 7)) << 4);
            uint32_t qh[4], ql[4];
            ldsm_x4(qh, sQh + qoff);
            ldsm_x4(ql, sQl + qoff);
#pragma unroll
            for (int g = 0; g < 4; g++) {
                int kr = g * 16 + (lane & 15);
                uint32_t koff = kr * 256 + ((c ^ (kr & 7)) << 4);
                uint32_t th[4], tl[4];
                ldsm_x4(th, sKh + koff);
                ldsm_x4(tl, sKl + koff);
                uint32_t b0h[2] = {th[0], th[2]}, b1h[2] = {th[1], th[3]};
                uint32_t b0l[2] = {tl[0], tl[2]}, b1l[2] = {tl[1], tl[3]};
                mma_16816(s[2 * g],     qh, b0h);
                mma_16816(s[2 * g],     qh, b0l);
                mma_16816(s[2 * g],     ql, b0h);
                mma_16816(s[2 * g + 1], qh, b1h);
                mma_16816(s[2 * g + 1], qh, b1l);
                mma_16816(s[2 * g + 1], ql, b1h);
            }
        }

        if (kt >= 2 * qt) {
            const int q0 = qt * 128 + wid * 16 + (lane >> 2);
            const int k0 = kt * 64 + (lane & 3) * 2;
#pragma unroll
            for (int nb = 0; nb < 8; nb++)
#pragma unroll
                for (int t = 0; t < 4; t++) {
                    int kg = k0 + nb * 8 + (t & 1);
                    int qg = q0 + (t >> 1) * 8;
                    if (kg > qg) s[nb][t] = -INFINITY;
                }
        }

        float mx0 = -INFINITY, mx1 = -INFINITY;
#pragma unroll
        for (int nb = 0; nb < 8; nb++) {
            mx0 = fmaxf(mx0, fmaxf(s[nb][0], s[nb][1]));
            mx1 = fmaxf(mx1, fmaxf(s[nb][2], s[nb][3]));
        }
        mx0 = fmaxf(mx0, __shfl_xor_sync(0xffffffffu, mx0, 1));
        mx0 = fmaxf(mx0, __shfl_xor_sync(0xffffffffu, mx0, 2));
        mx1 = fmaxf(mx1, __shfl_xor_sync(0xffffffffu, mx1, 1));
        mx1 = fmaxf(mx1, __shfl_xor_sync(0xffffffffu, mx1, 2));
        float mn0 = fmaxf(m0, mx0), mn1 = fmaxf(m1, mx1);

        bool need = !__all_sync(0xffffffffu, (m0 == mn0) && (m1 == mn1));
        if (need) {
            float c0 = fexp2(m0 - mn0), c1 = fexp2(m1 - mn1);
            l0 *= c0; l1 *= c1;
#pragma unroll
            for (int nb = 0; nb < 16; nb++) {
                o[nb][0] *= c0; o[nb][1] *= c0;
                o[nb][2] *= c1; o[nb][3] *= c1;
            }
            m0 = mn0; m1 = mn1;
        }

        float rs0 = 0.f, rs1 = 0.f;
#pragma unroll
        for (int nb = 0; nb < 8; nb++) {
            s[nb][0] = fexp2(s[nb][0] - m0);
            s[nb][1] = fexp2(s[nb][1] - m0);
            s[nb][2] = fexp2(s[nb][2] - m1);
            s[nb][3] = fexp2(s[nb][3] - m1);
            rs0 += s[nb][0] + s[nb][1];
            rs1 += s[nb][2] + s[nb][3];
        }
        rs0 += __shfl_xor_sync(0xffffffffu, rs0, 1);
        rs0 += __shfl_xor_sync(0xffffffffu, rs0, 2);
        rs1 += __shfl_xor_sync(0xffffffffu, rs1, 1);
        rs1 += __shfl_xor_sync(0xffffffffu, rs1, 2);
        l0 += rs0;
        l1 += rs1;

        uint32_t ph[4][4], pl[4][4];
#pragma unroll
        for (int j = 0; j < 4; j++) {
            split2(s[2 * j][0],     s[2 * j][1],     ph[j][0], pl[j][0]);
            split2(s[2 * j][2],     s[2 * j][3],     ph[j][1], pl[j][1]);
            split2(s[2 * j + 1][0], s[2 * j + 1][1], ph[j][2], pl[j][2]);
            split2(s[2 * j + 1][2], s[2 * j + 1][3], ph[j][3], pl[j][3]);
        }

#pragma unroll
        for (int ks = 0; ks < 4; ks++) {
            const int vr = ks * 16 + (lane & 15);
#pragma unroll
            for (int db = 0; db < 8; db++) {
                const int c = db * 2 + (lane >> 4);
                uint32_t voff = vr * 256 + ((c ^ (vr & 7)) << 4);
                uint32_t th[4], tl[4];
                ldsm_x4_t(th, sVh + voff);
                ldsm_x4_t(tl, sVl + voff);
                uint32_t b0h[2] = {th[0], th[1]}, b1h[2] = {th[2], th[3]};
                uint32_t b0l[2] = {tl[0], tl[1]}, b1l[2] = {tl[2], tl[3]};
                mma_16816(o[2 * db],     ph[ks], b0h);
                mma_16816(o[2 * db],     ph[ks], b0l);
                mma_16816(o[2 * db],     pl[ks], b0h);
                mma_16816(o[2 * db + 1], ph[ks], b1h);
                mma_16816(o[2 * db + 1], ph[ks], b1l);
                mma_16816(o[2 * db + 1], pl[ks], b1h);
            }
        }
    }

    const int b = bh >> 4, h = bh & 15;
    const float i0 = 1.f / l0, i1 = 1.f / l1;
    const int r0 = qt * 128 + wid * 16 + (lane >> 2);
#pragma unroll
    for (int half = 0; half < 2; half++) {
        const int srow = r0 + half * 8;
        const float inv = half ? i1 : i0;
        const size_t base = ((size_t)b * SEQ + srow) * HIDDIM + (size_t)h * HDIM + (lane & 3) * 2;
#pragma unroll
        for (int nb = 0; nb < 16; nb++) {
            uint32_t hw, lw;
            split2(o[nb][half * 2] * inv, o[nb][half * 2 + 1] * inv, hw, lw);
            *(uint32_t*)(chi + base + nb * 8) = hw;
            *(uint32_t*)(clo + base + nb * 8) = lw;
        }
    }
}

// ---------------------------------------------------------------------------
extern "C" void kernel_launch(void* const* d_in, const int* in_sizes, int n_in,
                              void* d_out, int out_size)
{
    const float* x  = (const float*)d_in[0];
    const float* Wq = (const float*)d_in[1];
    const float* Wk = (const float*)d_in[2];
    const float* Wv = (const float*)d_in[3];
    const float* Wo = (const float*)d_in[4];

    float* out = (float*)d_out;                          // [B,S,HID]
    float* kv  = out + (size_t)BSZ * SEQ * HIDDIM;       // [B,H,2,S,D]

    __nv_bfloat16 *xhi, *xlo, *whi, *wlo, *chi, *clo;
    __nv_bfloat16 *qhi, *qlo, *khi, *klo, *vhi, *vlo;
    cudaGetSymbolAddress((void**)&xhi, g_xhi);
    cudaGetSymbolAddress((void**)&xlo, g_xlo);
    cudaGetSymbolAddress((void**)&whi, g_whi);
    cudaGetSymbolAddress((void**)&wlo, g_wlo);
    cudaGetSymbolAddress((void**)&chi, g_chi);
    cudaGetSymbolAddress((void**)&clo, g_clo);
    cudaGetSymbolAddress((void**)&qhi, g_qhi);
    cudaGetSymbolAddress((void**)&qlo, g_qlo);
    cudaGetSymbolAddress((void**)&khi, g_khi);
    cudaGetSymbolAddress((void**)&klo, g_klo);
    cudaGetSymbolAddress((void**)&vhi, g_vhi);
    cudaGetSymbolAddress((void**)&vlo, g_vlo);

    const size_t WN = (size_t)HIDDIM * HIDDIM;

    // splits
    {
        int n4x = (int)((size_t)MTOT * HIDDIM / 4);
        split_f32<<<(n4x + 255) / 256, 256>>>(x, xhi, xlo, n4x);
        int n4w = (int)(4 * WN / 4);
        split_w4<<<(n4w + 255) / 256, 256>>>(Wq, Wk, Wv, Wo, whi, wlo);
    }

    const int gsmem = 2 * STG_B;                         // 192 KB
    cudaFuncSetAttribute(gemm_mma, cudaFuncAttributeMaxDynamicSharedMemorySize, gsmem);

    // merged QKV projection: N = 6144 ([Wq|Wk|Wv] row-contiguous), M-tiles of 256
    dim3 qkvgrid(3 * HIDDIM / 128, MTOT / 256);          // (48, 32)
    gemm_mma<<<qkvgrid, 256, gsmem>>>(xhi, xlo, whi, wlo, kv, 3,
                                      qhi, qlo, khi, klo, vhi, vlo);

    // tensor-core flash attention (exp2 domain)
    cudaFuncSetAttribute(flash_attn_tc, cudaFuncAttributeMaxDynamicSharedMemorySize, FA_SMEM);
    flash_attn_tc<<<dim3(SEQ / 128, BSZ * NH), 256, FA_SMEM>>>(
        qhi, qlo, khi, klo, vhi, vlo, chi, clo);

    // output projection
    dim3 ogrid(HIDDIM / 128, MTOT / 256);                // (16, 32)
    gemm_mma<<<ogrid, 256, gsmem>>>(chi, clo, whi + 3 * WN, wlo + 3 * WN, out, 0,
                                    nullptr, nullptr, nullptr, nullptr, nullptr, nullptr);
}

// round 17
// speedup vs baseline: 1.1203x; 1.1203x over previous
#include <cuda_runtime.h>
#include <cuda_bf16.h>
#include <math.h>
#include <stdint.h>

#define BSZ 4
#define SEQ 2048
#define HIDDIM 2048
#define NH 16
#define HDIM 128
#define MTOT (BSZ * SEQ)   // 8192
#define QKSCALE 0.08838834764831845f
#define QSCALE2 (QKSCALE * 1.4426950408889634f)   // fold log2(e): softmax in 2^x

// ---------------------------------------------------------------------------
// Scratch (static __device__ — no allocations allowed)
// ---------------------------------------------------------------------------
__device__ __nv_bfloat16 g_xhi[(size_t)MTOT * HIDDIM];
__device__ __nv_bfloat16 g_xlo[(size_t)MTOT * HIDDIM];
__device__ __nv_bfloat16 g_whi[(size_t)4 * HIDDIM * HIDDIM];   // [Wq|Wk|Wv|Wo]
__device__ __nv_bfloat16 g_wlo[(size_t)4 * HIDDIM * HIDDIM];
__device__ __nv_bfloat16 g_chi[(size_t)MTOT * HIDDIM];
__device__ __nv_bfloat16 g_clo[(size_t)MTOT * HIDDIM];
__device__ __nv_bfloat16 g_qhi[(size_t)MTOT * HIDDIM];         // [B,H,S,D] log2-scaled
__device__ __nv_bfloat16 g_qlo[(size_t)MTOT * HIDDIM];
__device__ __nv_bfloat16 g_khi[(size_t)MTOT * HIDDIM];
__device__ __nv_bfloat16 g_klo[(size_t)MTOT * HIDDIM];
__device__ __nv_bfloat16 g_vhi[(size_t)MTOT * HIDDIM];
__device__ __nv_bfloat16 g_vlo[(size_t)MTOT * HIDDIM];

// ---------------------------------------------------------------------------
// Portable (compute_80+) tensor-core helpers
// ---------------------------------------------------------------------------
__device__ __forceinline__ uint32_t smem_u32(const void* p) {
    uint32_t a;
    asm("{ .reg .u64 t; cvta.to.shared.u64 t, %1; cvt.u32.u64 %0, t; }" : "=r"(a) : "l"(p));
    return a;
}
__device__ __forceinline__ void cp_async16(uint32_t dst, const void* src) {
    asm volatile("cp.async.cg.shared.global [%0], [%1], 16;" :: "r"(dst), "l"(src) : "memory");
}
__device__ __forceinline__ void cp_commit() {
    asm volatile("cp.async.commit_group;" ::: "memory");
}
template <int N>
__device__ __forceinline__ void cp_wait() {
    asm volatile("cp.async.wait_group %0;" :: "n"(N) : "memory");
}
__device__ __forceinline__ void ldsm_x4(uint32_t* r, uint32_t addr) {
    asm volatile("ldmatrix.sync.aligned.m8n8.x4.shared.b16 {%0,%1,%2,%3}, [%4];"
                 : "=r"(r[0]), "=r"(r[1]), "=r"(r[2]), "=r"(r[3]) : "r"(addr));
}
__device__ __forceinline__ void ldsm_x4_t(uint32_t* r, uint32_t addr) {
    asm volatile("ldmatrix.sync.aligned.m8n8.x4.trans.shared.b16 {%0,%1,%2,%3}, [%4];"
                 : "=r"(r[0]), "=r"(r[1]), "=r"(r[2]), "=r"(r[3]) : "r"(addr));
}
__device__ __forceinline__ void mma_16816(float* c, const uint32_t* a, const uint32_t* b) {
    asm volatile(
        "mma.sync.aligned.m16n8k16.row.col.f32.bf16.bf16.f32 "
        "{%0,%1,%2,%3}, {%4,%5,%6,%7}, {%8,%9}, {%0,%1,%2,%3};"
        : "+f"(c[0]), "+f"(c[1]), "+f"(c[2]), "+f"(c[3])
        : "r"(a[0]), "r"(a[1]), "r"(a[2]), "r"(a[3]), "r"(b[0]), "r"(b[1]));
}

__device__ __forceinline__ void split2(float a, float b, uint32_t& hi, uint32_t& lo) {
    __nv_bfloat16 ha = __float2bfloat16_rn(a), hb = __float2bfloat16_rn(b);
    __nv_bfloat16 la = __float2bfloat16_rn(a - __bfloat162float(ha));
    __nv_bfloat16 lb = __float2bfloat16_rn(b - __bfloat162float(hb));
    hi = (uint32_t)__bfloat16_as_ushort(ha) | ((uint32_t)__bfloat16_as_ushort(hb) << 16);
    lo = (uint32_t)__bfloat16_as_ushort(la) | ((uint32_t)__bfloat16_as_ushort(lb) << 16);
}

// FFMA-pipe 2^x: x <= ~0, handles -inf via clamp. rel err ~1e-7.
__device__ __forceinline__ float fexp2(float t) {
    t = fmaxf(t, -126.0f);
    float fi = t + 12582912.0f;
    int i = __float_as_int(fi) - 0x4B400000;
    float r = t - (fi - 12582912.0f);
    float p = 1.8775767e-3f;
    p = fmaf(p, r, 8.9893397e-3f);
    p = fmaf(p, r, 5.5826318e-2f);
    p = fmaf(p, r, 2.4015361e-1f);
    p = fmaf(p, r, 6.9315308e-1f);
    p = fmaf(p, r, 1.0f);
    return p * __int_as_float((i + 127) << 23);
}

// ---------------------------------------------------------------------------
// fp32 -> bf16 hi/lo splits
// ---------------------------------------------------------------------------
__global__ void split_f32(const float* __restrict__ src, __nv_bfloat16* __restrict__ hi,
                          __nv_bfloat16* __restrict__ lo, int n4)
{
    int i = blockIdx.x * blockDim.x + threadIdx.x;
    if (i >= n4) return;
    float4 v = ((const float4*)src)[i];
    uint32_t h0, l0, h1, l1;
    split2(v.x, v.y, h0, l0);
    split2(v.z, v.w, h1, l1);
    ((uint2*)hi)[i] = make_uint2(h0, h1);
    ((uint2*)lo)[i] = make_uint2(l0, l1);
}

__global__ void split_w4(const float* __restrict__ Wq, const float* __restrict__ Wk,
                         const float* __restrict__ Wv, const float* __restrict__ Wo,
                         __nv_bfloat16* __restrict__ hi, __nv_bfloat16* __restrict__ lo)
{
    const int per = (HIDDIM * HIDDIM) / 4;
    int i = blockIdx.x * blockDim.x + threadIdx.x;
    int w = i / per, j = i - w * per;
    const float* src = (w == 0) ? Wq : (w == 1) ? Wk : (w == 2) ? Wv : Wo;
    float4 v = ((const float4*)src)[j];
    uint32_t h0, l0, h1, l1;
    split2(v.x, v.y, h0, l0);
    split2(v.z, v.w, h1, l1);
    ((uint2*)hi)[i] = make_uint2(h0, h1);
    ((uint2*)lo)[i] = make_uint2(l0, l1);
}

// ---------------------------------------------------------------------------
// mma.sync bf16x3 NT GEMM, 128x64 CTA tile, 8 warps of 32x32, 2-stage
// cp.async (48 KB/stage = 96 KB total -> 2 CTAs/SM), 1 sync per K-chunk.
// mode 0: fp32 row-major C [M, HIDDIM]
// mode 3: merged QKV (N=6144): sel=col>>11 -> 0:q (scaled, split only),
//         1:k / 2:v (fp32 kv cache + split)
// ---------------------------------------------------------------------------
#define KC 64
#define GA_B  (128 * 128)            // 16 KB: A half (hi or lo), 128 rows x 128B
#define GB_B  (64 * 128)             // 8 KB:  B half, 64 rows x 128B
#define GSTG  (2 * GA_B + 2 * GB_B)  // 48 KB per stage
#define NCHUNK (HIDDIM / KC)         // 32

__global__ void __launch_bounds__(256, 2)
gemm_mma(const __nv_bfloat16* __restrict__ Ahi, const __nv_bfloat16* __restrict__ Alo,
         const __nv_bfloat16* __restrict__ Bhi, const __nv_bfloat16* __restrict__ Blo,
         float* __restrict__ C, int mode,
         __nv_bfloat16* __restrict__ qhi, __nv_bfloat16* __restrict__ qlo,
         __nv_bfloat16* __restrict__ khi, __nv_bfloat16* __restrict__ klo,
         __nv_bfloat16* __restrict__ vhi, __nv_bfloat16* __restrict__ vlo)
{
    extern __shared__ char dsm[];
    const int tid  = threadIdx.x;
    const int wid  = tid >> 5;
    const int lane = tid & 31;
    const int wm   = wid >> 1;           // 4 row-slabs of 32
    const int wn   = wid & 1;            // 2 col-slabs of 32
    const int bm = blockIdx.y * 128;
    const int bn = blockIdx.x * 64;
    const uint32_t smb = smem_u32(dsm);

    float acc[2][4][4];
#pragma unroll
    for (int mi = 0; mi < 2; mi++)
#pragma unroll
        for (int ni = 0; ni < 4; ni++)
#pragma unroll
            for (int t = 0; t < 4; t++) acc[mi][ni][t] = 0.f;

    const int lr = tid >> 3;             // 0..31
    const int lc = tid & 7;

    auto issue_stage = [&](int st, int kc) {
        uint32_t sbase = smb + st * GSTG;
        const size_t kb = (size_t)kc * KC;
#pragma unroll
        for (int it = 0; it < 4; it++) {                 // A: 128 rows
            int r = lr + it * 32;
            int sw = ((lc ^ (r & 7)) << 4);
            size_t ga = (size_t)(bm + r) * HIDDIM + kb + lc * 8;
            cp_async16(sbase + r * 128 + sw,         Ahi + ga);
            cp_async16(sbase + GA_B + r * 128 + sw,  Alo + ga);
        }
#pragma unroll
        for (int it = 0; it < 2; it++) {                 // B: 64 rows
            int r = lr + it * 32;
            int sw = ((lc ^ (r & 7)) << 4);
            size_t gb = (size_t)(bn + r) * HIDDIM + kb + lc * 8;
            cp_async16(sbase + 2 * GA_B + r * 128 + sw,         Bhi + gb);
            cp_async16(sbase + 2 * GA_B + GB_B + r * 128 + sw,  Blo + gb);
        }
        cp_commit();
    };

    issue_stage(0, 0);

    for (int kc = 0; kc < NCHUNK; kc++) {
        cp_wait<0>();
        __syncthreads();                 // data visible + prior stage retired
        if (kc + 1 < NCHUNK) issue_stage((kc + 1) & 1, kc + 1);

        const uint32_t sb = smb + (kc & 1) * GSTG;
        const int arow_l = (lane & 15);
        const int koff_l = (lane >> 4);

#pragma unroll
        for (int ks = 0; ks < 4; ks++) {
            const int chunk = ks * 2 + koff_l;
            uint32_t ahi[2][4], alo[2][4];
#pragma unroll
            for (int mi = 0; mi < 2; mi++) {
                int r = wm * 32 + mi * 16 + arow_l;
                uint32_t off = (uint32_t)(r * 128 + ((chunk ^ (r & 7)) << 4));
                ldsm_x4(ahi[mi], sb + off);
                ldsm_x4(alo[mi], sb + GA_B + off);
            }
            uint32_t bhi[4][2], blo[4][2];
#pragma unroll
            for (int g = 0; g < 2; g++) {
                int r = wn * 32 + g * 16 + arow_l;
                uint32_t off = (uint32_t)(r * 128 + ((chunk ^ (r & 7)) << 4));
                uint32_t t[4];
                ldsm_x4(t, sb + 2 * GA_B + off);
                bhi[g * 2 + 0][0] = t[0]; bhi[g * 2 + 1][0] = t[1];
                bhi[g * 2 + 0][1] = t[2]; bhi[g * 2 + 1][1] = t[3];
                ldsm_x4(t, sb + 2 * GA_B + GB_B + off);
                blo[g * 2 + 0][0] = t[0]; blo[g * 2 + 1][0] = t[1];
                blo[g * 2 + 0][1] = t[2]; blo[g * 2 + 1][1] = t[3];
            }
#pragma unroll
            for (int mi = 0; mi < 2; mi++)
#pragma unroll
                for (int ni = 0; ni < 4; ni++) {
                    mma_16816(acc[mi][ni], ahi[mi], bhi[ni]);
                    mma_16816(acc[mi][ni], ahi[mi], blo[ni]);
                    mma_16816(acc[mi][ni], alo[mi], bhi[ni]);
                }
        }
    }

    // epilogue
#pragma unroll
    for (int mi = 0; mi < 2; mi++) {
        const int row0 = bm + wm * 32 + mi * 16 + (lane >> 2);
#pragma unroll
        for (int half = 0; half < 2; half++) {
            const int row = row0 + half * 8;
            const int b = row >> 11, s = row & 2047;
#pragma unroll
            for (int ni = 0; ni < 4; ni++) {
                const int col = bn + wn * 32 + ni * 8 + (lane & 3) * 2;
                float v0 = acc[mi][ni][half * 2 + 0];
                float v1 = acc[mi][ni][half * 2 + 1];
                if (mode == 0) {
                    *(float2*)(C + (size_t)row * HIDDIM + col) = make_float2(v0, v1);
                } else {
                    const int sel = col >> 11;          // 0 q, 1 k, 2 v
                    const int cm = col & 2047;
                    const int h = cm >> 7, d = cm & 127;
                    const size_t sc = (((size_t)b * NH + h) * SEQ + s) * HDIM + d;
                    uint32_t hw, lw;
                    if (sel == 0) {
                        split2(v0 * QSCALE2, v1 * QSCALE2, hw, lw);
                        *(uint32_t*)(qhi + sc) = hw;
                        *(uint32_t*)(qlo + sc) = lw;
                    } else {
                        size_t kva = ((((size_t)b * NH + h) * 2 + (sel - 1)) * SEQ + s) * HDIM + d;
                        *(float2*)(C + kva) = make_float2(v0, v1);
                        split2(v0, v1, hw, lw);
                        __nv_bfloat16* sh = (sel == 1) ? khi : vhi;
                        __nv_bfloat16* sl = (sel == 1) ? klo : vlo;
                        *(uint32_t*)(sh + sc) = hw;
                        *(uint32_t*)(sl + sc) = lw;
                    }
                }
            }
        }
    }
}

// ---------------------------------------------------------------------------
// Tensor-core flash attention: causal, q-tile 128, k-tile 64, 8 warps,
// exp2-domain online softmax, single __syncthreads per k-tile. (R13-proven)
// ---------------------------------------------------------------------------
#define FA_SMEM (65536 + 2 * 65536)   // 192 KB

__global__ void __launch_bounds__(256, 1)
flash_attn_tc(const __nv_bfloat16* __restrict__ Qhi, const __nv_bfloat16* __restrict__ Qlo,
              const __nv_bfloat16* __restrict__ Khi, const __nv_bfloat16* __restrict__ Klo,
              const __nv_bfloat16* __restrict__ Vhi, const __nv_bfloat16* __restrict__ Vlo,
              __nv_bfloat16* __restrict__ chi, __nv_bfloat16* __restrict__ clo)
{
    extern __shared__ char dsm[];
    const int tid = threadIdx.x, wid = tid >> 5, lane = tid & 31;
    const int qt = 15 - blockIdx.x;          // big tiles first
    const int bh = blockIdx.y;
    const uint32_t smb = smem_u32(dsm);
    const uint32_t sQh = smb, sQl = smb + 32768;

    const size_t bhb = (size_t)bh * SEQ * HDIM;
    const __nv_bfloat16* qh_g = Qhi + bhb + (size_t)qt * 128 * HDIM;
    const __nv_bfloat16* ql_g = Qlo + bhb + (size_t)qt * 128 * HDIM;

#pragma unroll
    for (int it = 0; it < 8; it++) {
        int idx = tid + it * 256;
        int r = idx >> 4, c = idx & 15;
        uint32_t off = r * 256 + ((c ^ (r & 7)) << 4);
        int g = r * 128 + c * 8;
        cp_async16(sQh + off, qh_g + g);
        cp_async16(sQl + off, ql_g + g);
    }

    auto load_kv = [&](int st, int kt) {
        uint32_t sb = smb + 65536 + st * 65536;
        const size_t tb = bhb + (size_t)kt * 64 * HDIM;
#pragma unroll
        for (int it = 0; it < 4; it++) {
            int idx = tid + it * 256;
            int r = idx >> 4, c = idx & 15;
            uint32_t off = r * 256 + ((c ^ (r & 7)) << 4);
            int g = r * 128 + c * 8;
            cp_async16(sb + off,         Khi + tb + g);
            cp_async16(sb + 16384 + off, Klo + tb + g);
            cp_async16(sb + 32768 + off, Vhi + tb + g);
            cp_async16(sb + 49152 + off, Vlo + tb + g);
        }
        cp_commit();
    };
    load_kv(0, 0);

    float o[16][4];
#pragma unroll
    for (int nb = 0; nb < 16; nb++)
#pragma unroll
        for (int t = 0; t < 4; t++) o[nb][t] = 0.f;
    float m0 = -INFINITY, m1 = -INFINITY, l0 = 0.f, l1 = 0.f;

    const int ktmax = 2 * qt + 1;
    for (int kt = 0; kt <= ktmax; kt++) {
        const int st = kt & 1;
        cp_wait<0>();
        __syncthreads();
        if (kt < ktmax) load_kv(st ^ 1, kt + 1);

        const uint32_t sb = smb + 65536 + st * 65536;
        const uint32_t sKh = sb, sKl = sb + 16384, sVh = sb + 32768, sVl = sb + 49152;

        float s[8][4];
#pragma unroll
        for (int nb = 0; nb < 8; nb++)
#pragma unroll
            for (int t = 0; t < 4; t++) s[nb][t] = 0.f;

#pragma unroll
        for (int ks = 0; ks < 8; ks++) {
            const int c = ks * 2 + (lane >> 4);
            const int qr = wid * 16 + (lane & 15);
            uint32_t qoff = qr * 256 + ((c ^ (qr & 7)) << 4);
            uint32_t qh[4], ql[4];
            ldsm_x4(qh, sQh + qoff);
            ldsm_x4(ql, sQl + qoff);
#pragma unroll
            for (int g = 0; g < 4; g++) {
                int kr = g * 16 + (lane & 15);
                uint32_t koff = kr * 256 + ((c ^ (kr & 7)) << 4);
                uint32_t th[4], tl[4];
                ldsm_x4(th, sKh + koff);
                ldsm_x4(tl, sKl + koff);
                uint32_t b0h[2] = {th[0], th[2]}, b1h[2] = {th[1], th[3]};
                uint32_t b0l[2] = {tl[0], tl[2]}, b1l[2] = {tl[1], tl[3]};
                mma_16816(s[2 * g],     qh, b0h);
                mma_16816(s[2 * g],     qh, b0l);
                mma_16816(s[2 * g],     ql, b0h);
                mma_16816(s[2 * g + 1], qh, b1h);
                mma_16816(s[2 * g + 1], qh, b1l);
                mma_16816(s[2 * g + 1], ql, b1h);
            }
        }

        if (kt >= 2 * qt) {
            const int q0 = qt * 128 + wid * 16 + (lane >> 2);
            const int k0 = kt * 64 + (lane & 3) * 2;
#pragma unroll
            for (int nb = 0; nb < 8; nb++)
#pragma unroll
                for (int t = 0; t < 4; t++) {
                    int kg = k0 + nb * 8 + (t & 1);
                    int qg = q0 + (t >> 1) * 8;
                    if (kg > qg) s[nb][t] = -INFINITY;
                }
        }

        float mx0 = -INFINITY, mx1 = -INFINITY;
#pragma unroll
        for (int nb = 0; nb < 8; nb++) {
            mx0 = fmaxf(mx0, fmaxf(s[nb][0], s[nb][1]));
            mx1 = fmaxf(mx1, fmaxf(s[nb][2], s[nb][3]));
        }
        mx0 = fmaxf(mx0, __shfl_xor_sync(0xffffffffu, mx0, 1));
        mx0 = fmaxf(mx0, __shfl_xor_sync(0xffffffffu, mx0, 2));
        mx1 = fmaxf(mx1, __shfl_xor_sync(0xffffffffu, mx1, 1));
        mx1 = fmaxf(mx1, __shfl_xor_sync(0xffffffffu, mx1, 2));
        float mn0 = fmaxf(m0, mx0), mn1 = fmaxf(m1, mx1);

        bool need = !__all_sync(0xffffffffu, (m0 == mn0) && (m1 == mn1));
        if (need) {
            float c0 = fexp2(m0 - mn0), c1 = fexp2(m1 - mn1);
            l0 *= c0; l1 *= c1;
#pragma unroll
            for (int nb = 0; nb < 16; nb++) {
                o[nb][0] *= c0; o[nb][1] *= c0;
                o[nb][2] *= c1; o[nb][3] *= c1;
            }
            m0 = mn0; m1 = mn1;
        }

        float rs0 = 0.f, rs1 = 0.f;
#pragma unroll
        for (int nb = 0; nb < 8; nb++) {
            s[nb][0] = fexp2(s[nb][0] - m0);
            s[nb][1] = fexp2(s[nb][1] - m0);
            s[nb][2] = fexp2(s[nb][2] - m1);
            s[nb][3] = fexp2(s[nb][3] - m1);
            rs0 += s[nb][0] + s[nb][1];
            rs1 += s[nb][2] + s[nb][3];
        }
        rs0 += __shfl_xor_sync(0xffffffffu, rs0, 1);
        rs0 += __shfl_xor_sync(0xffffffffu, rs0, 2);
        rs1 += __shfl_xor_sync(0xffffffffu, rs1, 1);
        rs1 += __shfl_xor_sync(0xffffffffu, rs1, 2);
        l0 += rs0;
        l1 += rs1;

        uint32_t ph[4][4], pl[4][4];
#pragma unroll
        for (int j = 0; j < 4; j++) {
            split2(s[2 * j][0],     s[2 * j][1],     ph[j][0], pl[j][0]);
            split2(s[2 * j][2],     s[2 * j][3],     ph[j][1], pl[j][1]);
            split2(s[2 * j + 1][0], s[2 * j + 1][1], ph[j][2], pl[j][2]);
            split2(s[2 * j + 1][2], s[2 * j + 1][3], ph[j][3], pl[j][3]);
        }

#pragma unroll
        for (int ks = 0; ks < 4; ks++) {
            const int vr = ks * 16 + (lane & 15);
#pragma unroll
            for (int db = 0; db < 8; db++) {
                const int c = db * 2 + (lane >> 4);
                uint32_t voff = vr * 256 + ((c ^ (vr & 7)) << 4);
                uint32_t th[4], tl[4];
                ldsm_x4_t(th, sVh + voff);
                ldsm_x4_t(tl, sVl + voff);
                uint32_t b0h[2] = {th[0], th[1]}, b1h[2] = {th[2], th[3]};
                uint32_t b0l[2] = {tl[0], tl[1]}, b1l[2] = {tl[2], tl[3]};
                mma_16816(o[2 * db],     ph[ks], b0h);
                mma_16816(o[2 * db],     ph[ks], b0l);
                mma_16816(o[2 * db],     pl[ks], b0h);
                mma_16816(o[2 * db + 1], ph[ks], b1h);
                mma_16816(o[2 * db + 1], ph[ks], b1l);
                mma_16816(o[2 * db + 1], pl[ks], b1h);
            }
        }
    }

    const int b = bh >> 4, h = bh & 15;
    const float i0 = 1.f / l0, i1 = 1.f / l1;
    const int r0 = qt * 128 + wid * 16 + (lane >> 2);
#pragma unroll
    for (int half = 0; half < 2; half++) {
        const int srow = r0 + half * 8;
        const float inv = half ? i1 : i0;
        const size_t base = ((size_t)b * SEQ + srow) * HIDDIM + (size_t)h * HDIM + (lane & 3) * 2;
#pragma unroll
        for (int nb = 0; nb < 16; nb++) {
            uint32_t hw, lw;
            split2(o[nb][half * 2] * inv, o[nb][half * 2 + 1] * inv, hw, lw);
            *(uint32_t*)(chi + base + nb * 8) = hw;
            *(uint32_t*)(clo + base + nb * 8) = lw;
        }
    }
}

// ---------------------------------------------------------------------------
extern "C" void kernel_launch(void* const* d_in, const int* in_sizes, int n_in,
                              void* d_out, int out_size)
{
    const float* x  = (const float*)d_in[0];
    const float* Wq = (const float*)d_in[1];
    const float* Wk = (const float*)d_in[2];
    const float* Wv = (const float*)d_in[3];
    const float* Wo = (const float*)d_in[4];

    float* out = (float*)d_out;                          // [B,S,HID]
    float* kv  = out + (size_t)BSZ * SEQ * HIDDIM;       // [B,H,2,S,D]

    __nv_bfloat16 *xhi, *xlo, *whi, *wlo, *chi, *clo;
    __nv_bfloat16 *qhi, *qlo, *khi, *klo, *vhi, *vlo;
    cudaGetSymbolAddress((void**)&xhi, g_xhi);
    cudaGetSymbolAddress((void**)&xlo, g_xlo);
    cudaGetSymbolAddress((void**)&whi, g_whi);
    cudaGetSymbolAddress((void**)&wlo, g_wlo);
    cudaGetSymbolAddress((void**)&chi, g_chi);
    cudaGetSymbolAddress((void**)&clo, g_clo);
    cudaGetSymbolAddress((void**)&qhi, g_qhi);
    cudaGetSymbolAddress((void**)&qlo, g_qlo);
    cudaGetSymbolAddress((void**)&khi, g_khi);
    cudaGetSymbolAddress((void**)&klo, g_klo);
    cudaGetSymbolAddress((void**)&vhi, g_vhi);
    cudaGetSymbolAddress((void**)&vlo, g_vlo);

    const size_t WN = (size_t)HIDDIM * HIDDIM;

    // splits
    {
        int n4x = (int)((size_t)MTOT * HIDDIM / 4);
        split_f32<<<(n4x + 255) / 256, 256>>>(x, xhi, xlo, n4x);
        int n4w = (int)(4 * WN / 4);
        split_w4<<<(n4w + 255) / 256, 256>>>(Wq, Wk, Wv, Wo, whi, wlo);
    }

    const int gsmem = 2 * GSTG;                          // 96 KB -> 2 CTAs/SM
    cudaFuncSetAttribute(gemm_mma, cudaFuncAttributeMaxDynamicSharedMemorySize, gsmem);

    // merged QKV projection: N = 6144 ([Wq|Wk|Wv] row-contiguous)
    dim3 qkvgrid(3 * HIDDIM / 64, MTOT / 128);           // (96, 64)
    gemm_mma<<<qkvgrid, 256, gsmem>>>(xhi, xlo, whi, wlo, kv, 3,
                                      qhi, qlo, khi, klo, vhi, vlo);

    // tensor-core flash attention (exp2 domain)
    cudaFuncSetAttribute(flash_attn_tc, cudaFuncAttributeMaxDynamicSharedMemorySize, FA_SMEM);
    flash_attn_tc<<<dim3(SEQ / 128, BSZ * NH), 256, FA_SMEM>>>(
        qhi, qlo, khi, klo, vhi, vlo, chi, clo);

    // output projection
    dim3 ogrid(HIDDIM / 64, MTOT / 128);                 // (32, 64)
    gemm_mma<<<ogrid, 256, gsmem>>>(chi, clo, whi + 3 * WN, wlo + 3 * WN, out, 0,
                                    nullptr, nullptr, nullptr, nullptr, nullptr, nullptr);
}